// round 10
// baseline (speedup 1.0000x reference)
#include <cuda_runtime.h>
#include <cuda_fp16.h>
#include <math.h>
#include <stdint.h>

// Problem constants
#define NB    2
#define TSEQ  2048
#define CDIM  2048
#define NH    16
#define NKV   4
#define HD    128
#define MROWS (NB * TSEQ)          // 4096
#define KVW   (2 * NKV * HD)       // 1024
#define KVHW  (NKV * HD)           // 512

// Scratch (no cudaMalloc allowed)
__device__ float  g_Q[(size_t)MROWS * CDIM];
__device__ float  g_KV[(size_t)MROWS * KVW];
__device__ __half g_Qh[(size_t)MROWS * CDIM];
__device__ __half g_Kh[(size_t)MROWS * KVHW];
__device__ __half g_Vth[(size_t)NB * NKV * HD * TSEQ];
__device__ __half g_Yh[(size_t)MROWS * CDIM];
__device__ __half g_Xh[(size_t)MROWS * CDIM];
__device__ __half g_Wqh[(size_t)CDIM * CDIM];
__device__ __half g_Wkvh[(size_t)KVW * CDIM];
__device__ __half g_Woh[(size_t)CDIM * CDIM];

// ---------------------------------------------------------------------------
// Helpers
// ---------------------------------------------------------------------------
__device__ __forceinline__ void mma_f16(float* c,
                                        uint32_t a0, uint32_t a1, uint32_t a2, uint32_t a3,
                                        uint32_t b0, uint32_t b1) {
    asm("mma.sync.aligned.m16n8k16.row.col.f32.f16.f16.f32 "
        "{%0,%1,%2,%3}, {%4,%5,%6,%7}, {%8,%9}, {%0,%1,%2,%3};\n"
        : "+f"(c[0]), "+f"(c[1]), "+f"(c[2]), "+f"(c[3])
        : "r"(a0), "r"(a1), "r"(a2), "r"(a3), "r"(b0), "r"(b1));
}

__device__ __forceinline__ void cp_async16(uint32_t smem_addr, const void* gptr) {
    asm volatile("cp.async.cg.shared.global [%0], [%1], 16;\n"
                 :: "r"(smem_addr), "l"(gptr));
}

// ---------------------------------------------------------------------------
// fp32 -> fp16 conversion (vectorized)
// ---------------------------------------------------------------------------
__global__ void f32_to_f16_kernel(const float* __restrict__ in, __half* __restrict__ out, int n4)
{
    int i = blockIdx.x * blockDim.x + threadIdx.x;
    if (i >= n4) return;
    float4 v = ((const float4*)in)[i];
    ((__half2*)out)[2 * i]     = __floats2half2_rn(v.x, v.y);
    ((__half2*)out)[2 * i + 1] = __floats2half2_rn(v.z, v.w);
}

// ---------------------------------------------------------------------------
// FP16 tensor-core NT GEMM: C[M,N] = A[M,K] * B[N,K]^T (fp32 accumulate).
// 128x128 CTA tile, 128 threads (4 warps 2x2), warp tile 64x64, BK=64.
// PAD2=72 halfs: fragment word addr (4*gid + tig) mod 32 -> conflict-free.
// ---------------------------------------------------------------------------
#define BK2   64
#define PAD2  72
#define ATILE (128 * PAD2)          // halfs per tile buffer (9216)
#define GEMM_SMEM (4 * ATILE * 2)   // 73728 bytes (2 bufs x A,B)

__global__ __launch_bounds__(128, 2) void gemm_f16_nt(
    const __half* __restrict__ A, const __half* __restrict__ B,
    float* __restrict__ C, int M, int N, int K)
{
    extern __shared__ __half smh[];

    const int tid  = threadIdx.x;
    const int bm   = blockIdx.y * 128;
    const int bn   = blockIdx.x * 128;
    const int warp = tid >> 5;
    const int lane = tid & 31;
    const int wm   = warp >> 1;        // 0..1
    const int wn   = warp & 1;         // 0..1
    const int gid  = lane >> 2;        // 0..7
    const int tig  = lane & 3;         // 0..3

    // loader: thread t copies row t of A tile and row t of B tile (128B each)
    const __half* gA = A + (size_t)(bm + tid) * K;
    const __half* gB = B + (size_t)(bn + tid) * K;
    const int soff = tid * PAD2;

    float acc[4][8][4];
#pragma unroll
    for (int mt = 0; mt < 4; mt++)
#pragma unroll
        for (int nt = 0; nt < 8; nt++)
#pragma unroll
            for (int i = 0; i < 4; i++) acc[mt][nt][i] = 0.f;

    const int niter = K / BK2;

    {
        uint32_t sa = (uint32_t)__cvta_generic_to_shared(smh + soff);
        uint32_t sb = (uint32_t)__cvta_generic_to_shared(smh + ATILE + soff);
#pragma unroll
        for (int j = 0; j < 8; j++) {
            cp_async16(sa + j * 16, gA + j * 8);
            cp_async16(sb + j * 16, gB + j * 8);
        }
        asm volatile("cp.async.commit_group;\n" ::: "memory");
    }

    for (int k0 = 0; k0 < niter; k0++) {
        const int buf = k0 & 1;
        if (k0 + 1 < niter) {
            const int koff = (k0 + 1) * BK2;
            uint32_t sa = (uint32_t)__cvta_generic_to_shared(smh + (buf ^ 1) * 2 * ATILE + soff);
            uint32_t sb = sa + ATILE * 2;
#pragma unroll
            for (int j = 0; j < 8; j++) {
                cp_async16(sa + j * 16, gA + koff + j * 8);
                cp_async16(sb + j * 16, gB + koff + j * 8);
            }
        }
        asm volatile("cp.async.commit_group;\n" ::: "memory");
        asm volatile("cp.async.wait_group 1;\n" ::: "memory");
        __syncthreads();

        const __half* As = smh + buf * 2 * ATILE;
        const __half* Bs = As + ATILE;
#pragma unroll
        for (int ks = 0; ks < 4; ks++) {
            const int kc = ks * 16;
            uint32_t af[4][4], bf[8][2];
#pragma unroll
            for (int mt = 0; mt < 4; mt++) {
                const int r = wm * 64 + mt * 16 + gid;
                af[mt][0] = *(const uint32_t*)&As[r * PAD2 + kc + 2 * tig];
                af[mt][1] = *(const uint32_t*)&As[(r + 8) * PAD2 + kc + 2 * tig];
                af[mt][2] = *(const uint32_t*)&As[r * PAD2 + kc + 8 + 2 * tig];
                af[mt][3] = *(const uint32_t*)&As[(r + 8) * PAD2 + kc + 8 + 2 * tig];
            }
#pragma unroll
            for (int nt = 0; nt < 8; nt++) {
                const int r = wn * 64 + nt * 8 + gid;
                bf[nt][0] = *(const uint32_t*)&Bs[r * PAD2 + kc + 2 * tig];
                bf[nt][1] = *(const uint32_t*)&Bs[r * PAD2 + kc + 8 + 2 * tig];
            }
#pragma unroll
            for (int mt = 0; mt < 4; mt++)
#pragma unroll
                for (int nt = 0; nt < 8; nt++)
                    mma_f16(acc[mt][nt], af[mt][0], af[mt][1], af[mt][2], af[mt][3],
                            bf[nt][0], bf[nt][1]);
        }
        __syncthreads();
    }

#pragma unroll
    for (int mt = 0; mt < 4; mt++) {
        const int r0 = bm + wm * 64 + mt * 16 + gid;
#pragma unroll
        for (int nt = 0; nt < 8; nt++) {
            const int c0 = bn + wn * 64 + nt * 8 + tig * 2;
            *(float2*)&C[(size_t)r0 * N + c0]       = make_float2(acc[mt][nt][0], acc[mt][nt][1]);
            *(float2*)&C[(size_t)(r0 + 8) * N + c0] = make_float2(acc[mt][nt][2], acc[mt][nt][3]);
        }
    }
}

// ---------------------------------------------------------------------------
// RoPE -> fp16 emit (Q scaled; K compact), V -> fp16 transposed
// ---------------------------------------------------------------------------
__global__ void rope_q_half(const float* __restrict__ X, __half* __restrict__ O)
{
    int idx = blockIdx.x * blockDim.x + threadIdx.x;
    if (idx >= MROWS * NH * 64) return;
    int i   = idx & 63;
    int h   = (idx >> 6) % NH;
    int row = idx / (64 * NH);
    int t   = row & (TSEQ - 1);

    float freq = expf(-(float)i * (9.210340371976184f / 64.0f));
    float ang = (float)t * freq;
    float s, c;
    sincosf(ang, &s, &c);

    const float scale = 0.08838834764831845f;
    const float* p = X + (size_t)row * CDIM + h * 128;
    __half* o = O + (size_t)row * CDIM + h * 128;
    float x0 = p[i], x1 = p[i + 64];
    o[i]      = __float2half((x0 * c - x1 * s) * scale);
    o[i + 64] = __float2half((x1 * c + x0 * s) * scale);
}

__global__ void rope_k_half(const float* __restrict__ KV, __half* __restrict__ O)
{
    int idx = blockIdx.x * blockDim.x + threadIdx.x;
    if (idx >= MROWS * NKV * 64) return;
    int i   = idx & 63;
    int h   = (idx >> 6) % NKV;
    int row = idx / (64 * NKV);
    int t   = row & (TSEQ - 1);

    float freq = expf(-(float)i * (9.210340371976184f / 64.0f));
    float ang = (float)t * freq;
    float s, c;
    sincosf(ang, &s, &c);

    const float* p = KV + (size_t)row * KVW + h * 128;
    __half* o = O + (size_t)row * KVHW + h * 128;
    float x0 = p[i], x1 = p[i + 64];
    o[i]      = __float2half(x0 * c - x1 * s);
    o[i + 64] = __float2half(x1 * c + x0 * s);
}

__global__ void v_transpose_half(const float* __restrict__ KV, __half* __restrict__ Vt)
{
    __shared__ float tile[32][33];
    const int bk = blockIdx.z;
    const int b  = bk / NKV, kv = bk % NKV;
    const int t0 = blockIdx.x * 32;
    const int d0 = blockIdx.y * 32;
    const int tx = threadIdx.x, ty = threadIdx.y;

#pragma unroll
    for (int i = ty; i < 32; i += 8)
        tile[i][tx] = KV[(size_t)(b * TSEQ + t0 + i) * KVW + KVHW + kv * 128 + d0 + tx];
    __syncthreads();
#pragma unroll
    for (int i = ty; i < 32; i += 8)
        Vt[((size_t)bk * HD + d0 + i) * TSEQ + t0 + tx] = __float2half(tile[tx][i]);
}

// ---------------------------------------------------------------------------
// FP16 tensor-core causal flash attention (fp32 softmax/accum). (R9 body)
// ---------------------------------------------------------------------------
#define KPADH 136
#define VPADH 40
#define PPADH 40
#define KTILEH (32 * KPADH)
#define VTILEH (128 * VPADH)
#define BUFH   (KTILEH + VTILEH)
#define ATTN_SMEM ((2 * BUFH + 64 * PPADH) * 2)   // 43008 bytes

__global__ __launch_bounds__(128, 2) void attn_f16_kernel(
    const __half* __restrict__ Qh, const __half* __restrict__ Kh,
    const __half* __restrict__ Vt, __half* __restrict__ Y)
{
    extern __shared__ __half smh[];
    __half* Ps = smh + 2 * BUFH;

    const int b   = blockIdx.z;
    const int h   = blockIdx.y;
    const int q0  = blockIdx.x * 64;
    const int kvh = h >> 2;
    const int tid  = threadIdx.x;
    const int warp = tid >> 5;
    const int lane = tid & 31;
    const int gid  = lane >> 2;
    const int tig  = lane & 3;

    uint32_t qf[8][4];
    {
        const __half* qp  = Qh + (size_t)(b * TSEQ + q0 + warp * 16 + gid) * CDIM + h * 128;
        const __half* qp8 = qp + 8 * CDIM;
#pragma unroll
        for (int ks = 0; ks < 8; ks++) {
            qf[ks][0] = *(const uint32_t*)&qp [ks * 16 + 2 * tig];
            qf[ks][1] = *(const uint32_t*)&qp8[ks * 16 + 2 * tig];
            qf[ks][2] = *(const uint32_t*)&qp [ks * 16 + 8 + 2 * tig];
            qf[ks][3] = *(const uint32_t*)&qp8[ks * 16 + 8 + 2 * tig];
        }
    }

    float o[16][4];
#pragma unroll
    for (int nt = 0; nt < 16; nt++)
#pragma unroll
        for (int i = 0; i < 4; i++) o[nt][i] = 0.f;
    float m0 = -1e30f, m1 = -1e30f, l0 = 0.f, l1 = 0.f;

    const int nkt = q0 / 32 + 2;

    const __half* Kbase  = Kh + (size_t)(b * TSEQ) * KVHW + kvh * 128;
    const __half* Vtbase = Vt + ((size_t)(b * NKV + kvh) * HD) * TSEQ;

    {
        __half* Kb = smh;
        __half* Vb = smh + KTILEH;
#pragma unroll
        for (int i = 0; i < 4; i++) {
            int idx = tid + i * 128;
            int kr = idx >> 4, kc = idx & 15;
            cp_async16((uint32_t)__cvta_generic_to_shared(Kb + kr * KPADH + kc * 8),
                       Kbase + (size_t)kr * KVHW + kc * 8);
            int vr = idx >> 2, vc = idx & 3;
            cp_async16((uint32_t)__cvta_generic_to_shared(Vb + vr * VPADH + vc * 8),
                       Vtbase + (size_t)vr * TSEQ + vc * 8);
        }
        asm volatile("cp.async.commit_group;\n" ::: "memory");
    }

    const int row0 = warp * 16 + gid;

    for (int t = 0; t < nkt; t++) {
        const int buf = t & 1;
        if (t + 1 < nkt) {
            const int s1 = (t + 1) * 32;
            __half* Kb = smh + (buf ^ 1) * BUFH;
            __half* Vb = Kb + KTILEH;
#pragma unroll
            for (int i = 0; i < 4; i++) {
                int idx = tid + i * 128;
                int kr = idx >> 4, kc = idx & 15;
                cp_async16((uint32_t)__cvta_generic_to_shared(Kb + kr * KPADH + kc * 8),
                           Kbase + (size_t)(s1 + kr) * KVHW + kc * 8);
                int vr = idx >> 2, vc = idx & 3;
                cp_async16((uint32_t)__cvta_generic_to_shared(Vb + vr * VPADH + vc * 8),
                           Vtbase + (size_t)vr * TSEQ + s1 + vc * 8);
            }
        }
        asm volatile("cp.async.commit_group;\n" ::: "memory");
        asm volatile("cp.async.wait_group 1;\n" ::: "memory");
        __syncthreads();

        const __half* Kb = smh + buf * BUFH;
        const __half* Vb = Kb + KTILEH;
        const int s0 = t * 32;

        float s[4][4];
#pragma unroll
        for (int nt = 0; nt < 4; nt++)
#pragma unroll
            for (int i = 0; i < 4; i++) s[nt][i] = 0.f;

#pragma unroll
        for (int ks = 0; ks < 8; ks++) {
            const int kc = ks * 16;
#pragma unroll
            for (int nt = 0; nt < 4; nt++) {
                const __half* kr = Kb + (nt * 8 + gid) * KPADH + kc + 2 * tig;
                uint32_t b0 = *(const uint32_t*)kr;
                uint32_t b1 = *(const uint32_t*)(kr + 8);
                mma_f16(s[nt], qf[ks][0], qf[ks][1], qf[ks][2], qf[ks][3], b0, b1);
            }
        }

        if (t >= nkt - 2) {
            const int r0g = q0 + row0;
#pragma unroll
            for (int nt = 0; nt < 4; nt++) {
                const int c = s0 + nt * 8 + tig * 2;
                if (c > r0g)         s[nt][0] = -1e30f;
                if (c + 1 > r0g)     s[nt][1] = -1e30f;
                if (c > r0g + 8)     s[nt][2] = -1e30f;
                if (c + 1 > r0g + 8) s[nt][3] = -1e30f;
            }
        }

        float rm0 = s[0][0], rm1 = s[0][2];
#pragma unroll
        for (int nt = 0; nt < 4; nt++) {
            rm0 = fmaxf(rm0, fmaxf(s[nt][0], s[nt][1]));
            rm1 = fmaxf(rm1, fmaxf(s[nt][2], s[nt][3]));
        }
        rm0 = fmaxf(rm0, __shfl_xor_sync(0xffffffffu, rm0, 1));
        rm0 = fmaxf(rm0, __shfl_xor_sync(0xffffffffu, rm0, 2));
        rm1 = fmaxf(rm1, __shfl_xor_sync(0xffffffffu, rm1, 1));
        rm1 = fmaxf(rm1, __shfl_xor_sync(0xffffffffu, rm1, 2));

        float mt0 = fmaxf(m0, rm0), mt1 = fmaxf(m1, rm1);
        float c0 = __expf(m0 - mt0), c1 = __expf(m1 - mt1);
        m0 = mt0; m1 = mt1;

        float rs0 = 0.f, rs1 = 0.f;
#pragma unroll
        for (int nt = 0; nt < 4; nt++) {
            s[nt][0] = __expf(s[nt][0] - m0); rs0 += s[nt][0];
            s[nt][1] = __expf(s[nt][1] - m0); rs0 += s[nt][1];
            s[nt][2] = __expf(s[nt][2] - m1); rs1 += s[nt][2];
            s[nt][3] = __expf(s[nt][3] - m1); rs1 += s[nt][3];
        }
        rs0 += __shfl_xor_sync(0xffffffffu, rs0, 1);
        rs0 += __shfl_xor_sync(0xffffffffu, rs0, 2);
        rs1 += __shfl_xor_sync(0xffffffffu, rs1, 1);
        rs1 += __shfl_xor_sync(0xffffffffu, rs1, 2);
        l0 = l0 * c0 + rs0;
        l1 = l1 * c1 + rs1;

#pragma unroll
        for (int nt = 0; nt < 16; nt++) {
            o[nt][0] *= c0; o[nt][1] *= c0;
            o[nt][2] *= c1; o[nt][3] *= c1;
        }

#pragma unroll
        for (int nt = 0; nt < 4; nt++) {
            *(__half2*)&Ps[row0 * PPADH + nt * 8 + 2 * tig]       = __floats2half2_rn(s[nt][0], s[nt][1]);
            *(__half2*)&Ps[(row0 + 8) * PPADH + nt * 8 + 2 * tig] = __floats2half2_rn(s[nt][2], s[nt][3]);
        }
        __syncwarp();

#pragma unroll
        for (int ks = 0; ks < 2; ks++) {
            const int kc = ks * 16;
            uint32_t a0 = *(const uint32_t*)&Ps[row0 * PPADH + kc + 2 * tig];
            uint32_t a1 = *(const uint32_t*)&Ps[(row0 + 8) * PPADH + kc + 2 * tig];
            uint32_t a2 = *(const uint32_t*)&Ps[row0 * PPADH + kc + 8 + 2 * tig];
            uint32_t a3 = *(const uint32_t*)&Ps[(row0 + 8) * PPADH + kc + 8 + 2 * tig];
#pragma unroll
            for (int nt = 0; nt < 16; nt++) {
                const __half* vr = Vb + (nt * 8 + gid) * VPADH + kc + 2 * tig;
                uint32_t b0 = *(const uint32_t*)vr;
                uint32_t b1 = *(const uint32_t*)(vr + 8);
                mma_f16(o[nt], a0, a1, a2, a3, b0, b1);
            }
        }
        __syncthreads();
    }

    const float inv0 = 1.f / l0, inv1 = 1.f / l1;
    __half* yp  = Y + (size_t)(b * TSEQ + q0 + row0) * CDIM + h * 128;
    __half* yp8 = yp + 8 * CDIM;
#pragma unroll
    for (int nt = 0; nt < 16; nt++) {
        const int c = nt * 8 + tig * 2;
        *(__half2*)&yp [c] = __floats2half2_rn(o[nt][0] * inv0, o[nt][1] * inv0);
        *(__half2*)&yp8[c] = __floats2half2_rn(o[nt][2] * inv1, o[nt][3] * inv1);
    }
}

// ---------------------------------------------------------------------------
extern "C" void kernel_launch(void* const* d_in, const int* in_sizes, int n_in,
                              void* d_out, int out_size)
{
    const float* x   = (const float*)d_in[0];
    const float* Wq  = (const float*)d_in[1];
    const float* Wkv = (const float*)d_in[2];
    const float* Wo  = (const float*)d_in[3];
    float* out = (float*)d_out;

    float *pQ, *pKV;
    __half *pQh, *pKh, *pVth, *pYh, *pXh, *pWqh, *pWkvh, *pWoh;
    cudaGetSymbolAddress((void**)&pQ,    g_Q);
    cudaGetSymbolAddress((void**)&pKV,   g_KV);
    cudaGetSymbolAddress((void**)&pQh,   g_Qh);
    cudaGetSymbolAddress((void**)&pKh,   g_Kh);
    cudaGetSymbolAddress((void**)&pVth,  g_Vth);
    cudaGetSymbolAddress((void**)&pYh,   g_Yh);
    cudaGetSymbolAddress((void**)&pXh,   g_Xh);
    cudaGetSymbolAddress((void**)&pWqh,  g_Wqh);
    cudaGetSymbolAddress((void**)&pWkvh, g_Wkvh);
    cudaGetSymbolAddress((void**)&pWoh,  g_Woh);

    cudaFuncSetAttribute(gemm_f16_nt, cudaFuncAttributeMaxDynamicSharedMemorySize, GEMM_SMEM);
    cudaFuncSetAttribute(attn_f16_kernel, cudaFuncAttributeMaxDynamicSharedMemorySize, ATTN_SMEM);

    // 0) convert GEMM inputs to fp16
    {
        int n;
        n = MROWS * CDIM / 4;  f32_to_f16_kernel<<<(n + 255) / 256, 256>>>(x,   pXh,   n);
        n = CDIM * CDIM / 4;   f32_to_f16_kernel<<<(n + 255) / 256, 256>>>(Wq,  pWqh,  n);
        n = KVW * CDIM / 4;    f32_to_f16_kernel<<<(n + 255) / 256, 256>>>(Wkv, pWkvh, n);
        n = CDIM * CDIM / 4;   f32_to_f16_kernel<<<(n + 255) / 256, 256>>>(Wo,  pWoh,  n);
    }

    // 1) Q = x @ Wq^T ; 2) KV = x @ Wkv^T  (fp16 in, fp32 out)
    gemm_f16_nt<<<dim3(CDIM / 128, MROWS / 128), 128, GEMM_SMEM>>>(pXh, pWqh, pQ, MROWS, CDIM, CDIM);
    gemm_f16_nt<<<dim3(KVW / 128, MROWS / 128), 128, GEMM_SMEM>>>(pXh, pWkvh, pKV, MROWS, KVW, CDIM);

    // 3) RoPE -> fp16 Q/K ; V -> fp16 transposed
    {
        int nq = MROWS * NH * 64;
        rope_q_half<<<(nq + 255) / 256, 256>>>(pQ, pQh);
        int nk = MROWS * NKV * 64;
        rope_k_half<<<(nk + 255) / 256, 256>>>(pKV, pKh);
        v_transpose_half<<<dim3(TSEQ / 32, HD / 32, NB * NKV), dim3(32, 8)>>>(pKV, pVth);
    }

    // 4) fp16 tensor-core causal flash attention (fp16 Y out)
    attn_f16_kernel<<<dim3(TSEQ / 64, NH, NB), 128, ATTN_SMEM>>>(pQh, pKh, pVth, pYh);

    // 5) out = Y @ Wo^T (fp16 in, fp32 out)
    gemm_f16_nt<<<dim3(CDIM / 128, MROWS / 128), 128, GEMM_SMEM>>>(pYh, pWoh, out, MROWS, CDIM, CDIM);
}

// round 11
// speedup vs baseline: 1.1436x; 1.1436x over previous
#include <cuda_runtime.h>
#include <cuda_fp16.h>
#include <math.h>
#include <stdint.h>

// Problem constants
#define NB    2
#define TSEQ  2048
#define CDIM  2048
#define NH    16
#define NKV   4
#define HD    128
#define MROWS (NB * TSEQ)          // 4096
#define KVW   (2 * NKV * HD)       // 1024
#define KVHW  (NKV * HD)           // 512

// Scratch (no cudaMalloc allowed)
__device__ float  g_Q[(size_t)MROWS * CDIM];
__device__ float  g_KV[(size_t)MROWS * KVW];
__device__ __half g_Qh[(size_t)MROWS * CDIM];
__device__ __half g_Kh[(size_t)MROWS * KVHW];
__device__ __half g_Vth[(size_t)NB * NKV * HD * TSEQ];
__device__ __half g_Yh[(size_t)MROWS * CDIM];
__device__ __half g_Xh[(size_t)MROWS * CDIM];
__device__ __half g_Wqh[(size_t)CDIM * CDIM];
__device__ __half g_Wkvh[(size_t)KVW * CDIM];
__device__ __half g_Woh[(size_t)CDIM * CDIM];

// ---------------------------------------------------------------------------
// Helpers
// ---------------------------------------------------------------------------
__device__ __forceinline__ void mma_f16(float* c,
                                        uint32_t a0, uint32_t a1, uint32_t a2, uint32_t a3,
                                        uint32_t b0, uint32_t b1) {
    asm("mma.sync.aligned.m16n8k16.row.col.f32.f16.f16.f32 "
        "{%0,%1,%2,%3}, {%4,%5,%6,%7}, {%8,%9}, {%0,%1,%2,%3};\n"
        : "+f"(c[0]), "+f"(c[1]), "+f"(c[2]), "+f"(c[3])
        : "r"(a0), "r"(a1), "r"(a2), "r"(a3), "r"(b0), "r"(b1));
}

__device__ __forceinline__ void cp_async16(uint32_t smem_addr, const void* gptr) {
    asm volatile("cp.async.cg.shared.global [%0], [%1], 16;\n"
                 :: "r"(smem_addr), "l"(gptr));
}

// ---------------------------------------------------------------------------
// fp32 -> fp16 conversion (vectorized)
// ---------------------------------------------------------------------------
__global__ void f32_to_f16_kernel(const float* __restrict__ in, __half* __restrict__ out, int n4)
{
    int i = blockIdx.x * blockDim.x + threadIdx.x;
    if (i >= n4) return;
    float4 v = ((const float4*)in)[i];
    ((__half2*)out)[2 * i]     = __floats2half2_rn(v.x, v.y);
    ((__half2*)out)[2 * i + 1] = __floats2half2_rn(v.z, v.w);
}

// ---------------------------------------------------------------------------
// FP16 tensor-core NT GEMM: C[M,N] = A[M,K] * B[N,K]^T (fp32 accumulate).
// R9 structure: 128x128 CTA tile, BK=32 halfs, 256 threads (8 warps 2x4),
// warp tile 64x32 — but with a 4-stage cp.async ring (loads issued 3 iters
// ahead ~1200cyc > 577cyc DRAM latency).
// PADH=40 halfs -> conflict-free .32 fragment loads.
// ---------------------------------------------------------------------------
#define BKH   32
#define PADH  40
#define TILEH (128 * PADH)            // halfs per A (or B) tile (5120)
#define NSTG  4
#define STGH  (2 * TILEH)             // halfs per stage (A+B)
#define GEMM_SMEM (NSTG * STGH * 2)   // 81920 bytes

__global__ __launch_bounds__(256, 2) void gemm_f16_nt(
    const __half* __restrict__ A, const __half* __restrict__ B,
    float* __restrict__ C, int M, int N, int K)
{
    extern __shared__ __half smh[];

    const int tid  = threadIdx.x;
    const int bm   = blockIdx.y * 128;
    const int bn   = blockIdx.x * 128;
    const int warp = tid >> 5;
    const int lane = tid & 31;
    const int wm   = warp >> 2;        // 0..1
    const int wn   = warp & 3;         // 0..3
    const int gid  = lane >> 2;        // 0..7
    const int tig  = lane & 3;         // 0..3

    // copy: each thread moves 32B (2x16B) of one row per tile
    const int crow = tid >> 1;         // 0..127
    const int cq   = tid & 1;          // 0..1
    const __half* gA = A + (size_t)(bm + crow) * K + cq * 16;
    const __half* gB = B + (size_t)(bn + crow) * K + cq * 16;
    const int soff = crow * PADH + cq * 16;   // halfs

    float acc[4][4][4];
#pragma unroll
    for (int mt = 0; mt < 4; mt++)
#pragma unroll
        for (int nt = 0; nt < 4; nt++)
#pragma unroll
            for (int i = 0; i < 4; i++) acc[mt][nt][i] = 0.f;

    const int niter = K / BKH;

    // prologue: stages for iters 0..NSTG-2
#pragma unroll
    for (int p = 0; p < NSTG - 1; p++) {
        const int koff = p * BKH;
        uint32_t sa = (uint32_t)__cvta_generic_to_shared(smh + p * STGH + soff);
        uint32_t sb = sa + TILEH * 2;
#pragma unroll
        for (int j = 0; j < 2; j++) {
            cp_async16(sa + j * 16, gA + koff + j * 8);
            cp_async16(sb + j * 16, gB + koff + j * 8);
        }
        asm volatile("cp.async.commit_group;\n" ::: "memory");
    }

    for (int k0 = 0; k0 < niter; k0++) {
        const int buf = k0 & (NSTG - 1);
        // issue loads for iter k0+NSTG-1 into buf (k0+NSTG-1)%NSTG
        // (that buffer was last read at iter k0-1; end-of-iter barrier protects it)
        if (k0 + NSTG - 1 < niter) {
            const int koff = (k0 + NSTG - 1) * BKH;
            uint32_t sa = (uint32_t)__cvta_generic_to_shared(
                smh + ((k0 + NSTG - 1) & (NSTG - 1)) * STGH + soff);
            uint32_t sb = sa + TILEH * 2;
#pragma unroll
            for (int j = 0; j < 2; j++) {
                cp_async16(sa + j * 16, gA + koff + j * 8);
                cp_async16(sb + j * 16, gB + koff + j * 8);
            }
        }
        asm volatile("cp.async.commit_group;\n" ::: "memory");
        asm volatile("cp.async.wait_group %0;\n" :: "n"(NSTG - 1) : "memory");
        __syncthreads();

        const __half* As = smh + buf * STGH;
        const __half* Bs = As + TILEH;
#pragma unroll
        for (int ks = 0; ks < 2; ks++) {
            const int kc = ks * 16;
            uint32_t af[4][4], bf[4][2];
#pragma unroll
            for (int mt = 0; mt < 4; mt++) {
                const int r = wm * 64 + mt * 16 + gid;
                af[mt][0] = *(const uint32_t*)&As[r * PADH + kc + 2 * tig];
                af[mt][1] = *(const uint32_t*)&As[(r + 8) * PADH + kc + 2 * tig];
                af[mt][2] = *(const uint32_t*)&As[r * PADH + kc + 8 + 2 * tig];
                af[mt][3] = *(const uint32_t*)&As[(r + 8) * PADH + kc + 8 + 2 * tig];
            }
#pragma unroll
            for (int nt = 0; nt < 4; nt++) {
                const int r = wn * 32 + nt * 8 + gid;
                bf[nt][0] = *(const uint32_t*)&Bs[r * PADH + kc + 2 * tig];
                bf[nt][1] = *(const uint32_t*)&Bs[r * PADH + kc + 8 + 2 * tig];
            }
#pragma unroll
            for (int mt = 0; mt < 4; mt++)
#pragma unroll
                for (int nt = 0; nt < 4; nt++)
                    mma_f16(acc[mt][nt], af[mt][0], af[mt][1], af[mt][2], af[mt][3],
                            bf[nt][0], bf[nt][1]);
        }
        __syncthreads();
    }

#pragma unroll
    for (int mt = 0; mt < 4; mt++) {
        const int r0 = bm + wm * 64 + mt * 16 + gid;
#pragma unroll
        for (int nt = 0; nt < 4; nt++) {
            const int c0 = bn + wn * 32 + nt * 8 + tig * 2;
            *(float2*)&C[(size_t)r0 * N + c0]       = make_float2(acc[mt][nt][0], acc[mt][nt][1]);
            *(float2*)&C[(size_t)(r0 + 8) * N + c0] = make_float2(acc[mt][nt][2], acc[mt][nt][3]);
        }
    }
}

// ---------------------------------------------------------------------------
// RoPE -> fp16 emit (Q scaled; K compact), V -> fp16 transposed
// ---------------------------------------------------------------------------
__global__ void rope_q_half(const float* __restrict__ X, __half* __restrict__ O)
{
    int idx = blockIdx.x * blockDim.x + threadIdx.x;
    if (idx >= MROWS * NH * 64) return;
    int i   = idx & 63;
    int h   = (idx >> 6) % NH;
    int row = idx / (64 * NH);
    int t   = row & (TSEQ - 1);

    float freq = expf(-(float)i * (9.210340371976184f / 64.0f));
    float ang = (float)t * freq;
    float s, c;
    sincosf(ang, &s, &c);

    const float scale = 0.08838834764831845f;
    const float* p = X + (size_t)row * CDIM + h * 128;
    __half* o = O + (size_t)row * CDIM + h * 128;
    float x0 = p[i], x1 = p[i + 64];
    o[i]      = __float2half((x0 * c - x1 * s) * scale);
    o[i + 64] = __float2half((x1 * c + x0 * s) * scale);
}

__global__ void rope_k_half(const float* __restrict__ KV, __half* __restrict__ O)
{
    int idx = blockIdx.x * blockDim.x + threadIdx.x;
    if (idx >= MROWS * NKV * 64) return;
    int i   = idx & 63;
    int h   = (idx >> 6) % NKV;
    int row = idx / (64 * NKV);
    int t   = row & (TSEQ - 1);

    float freq = expf(-(float)i * (9.210340371976184f / 64.0f));
    float ang = (float)t * freq;
    float s, c;
    sincosf(ang, &s, &c);

    const float* p = KV + (size_t)row * KVW + h * 128;
    __half* o = O + (size_t)row * KVHW + h * 128;
    float x0 = p[i], x1 = p[i + 64];
    o[i]      = __float2half(x0 * c - x1 * s);
    o[i + 64] = __float2half(x1 * c + x0 * s);
}

__global__ void v_transpose_half(const float* __restrict__ KV, __half* __restrict__ Vt)
{
    __shared__ float tile[32][33];
    const int bk = blockIdx.z;
    const int b  = bk / NKV, kv = bk % NKV;
    const int t0 = blockIdx.x * 32;
    const int d0 = blockIdx.y * 32;
    const int tx = threadIdx.x, ty = threadIdx.y;

#pragma unroll
    for (int i = ty; i < 32; i += 8)
        tile[i][tx] = KV[(size_t)(b * TSEQ + t0 + i) * KVW + KVHW + kv * 128 + d0 + tx];
    __syncthreads();
#pragma unroll
    for (int i = ty; i < 32; i += 8)
        Vt[((size_t)bk * HD + d0 + i) * TSEQ + t0 + tx] = __float2half(tile[tx][i]);
}

// ---------------------------------------------------------------------------
// FP16 tensor-core causal flash attention (fp32 softmax/accum). (R9 body)
// ---------------------------------------------------------------------------
#define KPADH 136
#define VPADH 40
#define PPADH 40
#define KTILEH (32 * KPADH)
#define VTILEH (128 * VPADH)
#define BUFH   (KTILEH + VTILEH)
#define ATTN_SMEM ((2 * BUFH + 64 * PPADH) * 2)   // 43008 bytes

__global__ __launch_bounds__(128, 2) void attn_f16_kernel(
    const __half* __restrict__ Qh, const __half* __restrict__ Kh,
    const __half* __restrict__ Vt, __half* __restrict__ Y)
{
    extern __shared__ __half smh[];
    __half* Ps = smh + 2 * BUFH;

    const int b   = blockIdx.z;
    const int h   = blockIdx.y;
    const int q0  = blockIdx.x * 64;
    const int kvh = h >> 2;
    const int tid  = threadIdx.x;
    const int warp = tid >> 5;
    const int lane = tid & 31;
    const int gid  = lane >> 2;
    const int tig  = lane & 3;

    uint32_t qf[8][4];
    {
        const __half* qp  = Qh + (size_t)(b * TSEQ + q0 + warp * 16 + gid) * CDIM + h * 128;
        const __half* qp8 = qp + 8 * CDIM;
#pragma unroll
        for (int ks = 0; ks < 8; ks++) {
            qf[ks][0] = *(const uint32_t*)&qp [ks * 16 + 2 * tig];
            qf[ks][1] = *(const uint32_t*)&qp8[ks * 16 + 2 * tig];
            qf[ks][2] = *(const uint32_t*)&qp [ks * 16 + 8 + 2 * tig];
            qf[ks][3] = *(const uint32_t*)&qp8[ks * 16 + 8 + 2 * tig];
        }
    }

    float o[16][4];
#pragma unroll
    for (int nt = 0; nt < 16; nt++)
#pragma unroll
        for (int i = 0; i < 4; i++) o[nt][i] = 0.f;
    float m0 = -1e30f, m1 = -1e30f, l0 = 0.f, l1 = 0.f;

    const int nkt = q0 / 32 + 2;

    const __half* Kbase  = Kh + (size_t)(b * TSEQ) * KVHW + kvh * 128;
    const __half* Vtbase = Vt + ((size_t)(b * NKV + kvh) * HD) * TSEQ;

    {
        __half* Kb = smh;
        __half* Vb = smh + KTILEH;
#pragma unroll
        for (int i = 0; i < 4; i++) {
            int idx = tid + i * 128;
            int kr = idx >> 4, kc = idx & 15;
            cp_async16((uint32_t)__cvta_generic_to_shared(Kb + kr * KPADH + kc * 8),
                       Kbase + (size_t)kr * KVHW + kc * 8);
            int vr = idx >> 2, vc = idx & 3;
            cp_async16((uint32_t)__cvta_generic_to_shared(Vb + vr * VPADH + vc * 8),
                       Vtbase + (size_t)vr * TSEQ + vc * 8);
        }
        asm volatile("cp.async.commit_group;\n" ::: "memory");
    }

    const int row0 = warp * 16 + gid;

    for (int t = 0; t < nkt; t++) {
        const int buf = t & 1;
        if (t + 1 < nkt) {
            const int s1 = (t + 1) * 32;
            __half* Kb = smh + (buf ^ 1) * BUFH;
            __half* Vb = Kb + KTILEH;
#pragma unroll
            for (int i = 0; i < 4; i++) {
                int idx = tid + i * 128;
                int kr = idx >> 4, kc = idx & 15;
                cp_async16((uint32_t)__cvta_generic_to_shared(Kb + kr * KPADH + kc * 8),
                           Kbase + (size_t)(s1 + kr) * KVHW + kc * 8);
                int vr = idx >> 2, vc = idx & 3;
                cp_async16((uint32_t)__cvta_generic_to_shared(Vb + vr * VPADH + vc * 8),
                           Vtbase + (size_t)vr * TSEQ + s1 + vc * 8);
            }
        }
        asm volatile("cp.async.commit_group;\n" ::: "memory");
        asm volatile("cp.async.wait_group 1;\n" ::: "memory");
        __syncthreads();

        const __half* Kb = smh + buf * BUFH;
        const __half* Vb = Kb + KTILEH;
        const int s0 = t * 32;

        float s[4][4];
#pragma unroll
        for (int nt = 0; nt < 4; nt++)
#pragma unroll
            for (int i = 0; i < 4; i++) s[nt][i] = 0.f;

#pragma unroll
        for (int ks = 0; ks < 8; ks++) {
            const int kc = ks * 16;
#pragma unroll
            for (int nt = 0; nt < 4; nt++) {
                const __half* kr = Kb + (nt * 8 + gid) * KPADH + kc + 2 * tig;
                uint32_t b0 = *(const uint32_t*)kr;
                uint32_t b1 = *(const uint32_t*)(kr + 8);
                mma_f16(s[nt], qf[ks][0], qf[ks][1], qf[ks][2], qf[ks][3], b0, b1);
            }
        }

        if (t >= nkt - 2) {
            const int r0g = q0 + row0;
#pragma unroll
            for (int nt = 0; nt < 4; nt++) {
                const int c = s0 + nt * 8 + tig * 2;
                if (c > r0g)         s[nt][0] = -1e30f;
                if (c + 1 > r0g)     s[nt][1] = -1e30f;
                if (c > r0g + 8)     s[nt][2] = -1e30f;
                if (c + 1 > r0g + 8) s[nt][3] = -1e30f;
            }
        }

        float rm0 = s[0][0], rm1 = s[0][2];
#pragma unroll
        for (int nt = 0; nt < 4; nt++) {
            rm0 = fmaxf(rm0, fmaxf(s[nt][0], s[nt][1]));
            rm1 = fmaxf(rm1, fmaxf(s[nt][2], s[nt][3]));
        }
        rm0 = fmaxf(rm0, __shfl_xor_sync(0xffffffffu, rm0, 1));
        rm0 = fmaxf(rm0, __shfl_xor_sync(0xffffffffu, rm0, 2));
        rm1 = fmaxf(rm1, __shfl_xor_sync(0xffffffffu, rm1, 1));
        rm1 = fmaxf(rm1, __shfl_xor_sync(0xffffffffu, rm1, 2));

        float mt0 = fmaxf(m0, rm0), mt1 = fmaxf(m1, rm1);
        float c0 = __expf(m0 - mt0), c1 = __expf(m1 - mt1);
        m0 = mt0; m1 = mt1;

        float rs0 = 0.f, rs1 = 0.f;
#pragma unroll
        for (int nt = 0; nt < 4; nt++) {
            s[nt][0] = __expf(s[nt][0] - m0); rs0 += s[nt][0];
            s[nt][1] = __expf(s[nt][1] - m0); rs0 += s[nt][1];
            s[nt][2] = __expf(s[nt][2] - m1); rs1 += s[nt][2];
            s[nt][3] = __expf(s[nt][3] - m1); rs1 += s[nt][3];
        }
        rs0 += __shfl_xor_sync(0xffffffffu, rs0, 1);
        rs0 += __shfl_xor_sync(0xffffffffu, rs0, 2);
        rs1 += __shfl_xor_sync(0xffffffffu, rs1, 1);
        rs1 += __shfl_xor_sync(0xffffffffu, rs1, 2);
        l0 = l0 * c0 + rs0;
        l1 = l1 * c1 + rs1;

#pragma unroll
        for (int nt = 0; nt < 16; nt++) {
            o[nt][0] *= c0; o[nt][1] *= c0;
            o[nt][2] *= c1; o[nt][3] *= c1;
        }

#pragma unroll
        for (int nt = 0; nt < 4; nt++) {
            *(__half2*)&Ps[row0 * PPADH + nt * 8 + 2 * tig]       = __floats2half2_rn(s[nt][0], s[nt][1]);
            *(__half2*)&Ps[(row0 + 8) * PPADH + nt * 8 + 2 * tig] = __floats2half2_rn(s[nt][2], s[nt][3]);
        }
        __syncwarp();

#pragma unroll
        for (int ks = 0; ks < 2; ks++) {
            const int kc = ks * 16;
            uint32_t a0 = *(const uint32_t*)&Ps[row0 * PPADH + kc + 2 * tig];
            uint32_t a1 = *(const uint32_t*)&Ps[(row0 + 8) * PPADH + kc + 2 * tig];
            uint32_t a2 = *(const uint32_t*)&Ps[row0 * PPADH + kc + 8 + 2 * tig];
            uint32_t a3 = *(const uint32_t*)&Ps[(row0 + 8) * PPADH + kc + 8 + 2 * tig];
#pragma unroll
            for (int nt = 0; nt < 16; nt++) {
                const __half* vr = Vb + (nt * 8 + gid) * VPADH + kc + 2 * tig;
                uint32_t b0 = *(const uint32_t*)vr;
                uint32_t b1 = *(const uint32_t*)(vr + 8);
                mma_f16(o[nt], a0, a1, a2, a3, b0, b1);
            }
        }
        __syncthreads();
    }

    const float inv0 = 1.f / l0, inv1 = 1.f / l1;
    __half* yp  = Y + (size_t)(b * TSEQ + q0 + row0) * CDIM + h * 128;
    __half* yp8 = yp + 8 * CDIM;
#pragma unroll
    for (int nt = 0; nt < 16; nt++) {
        const int c = nt * 8 + tig * 2;
        *(__half2*)&yp [c] = __floats2half2_rn(o[nt][0] * inv0, o[nt][1] * inv0);
        *(__half2*)&yp8[c] = __floats2half2_rn(o[nt][2] * inv1, o[nt][3] * inv1);
    }
}

// ---------------------------------------------------------------------------
extern "C" void kernel_launch(void* const* d_in, const int* in_sizes, int n_in,
                              void* d_out, int out_size)
{
    const float* x   = (const float*)d_in[0];
    const float* Wq  = (const float*)d_in[1];
    const float* Wkv = (const float*)d_in[2];
    const float* Wo  = (const float*)d_in[3];
    float* out = (float*)d_out;

    float *pQ, *pKV;
    __half *pQh, *pKh, *pVth, *pYh, *pXh, *pWqh, *pWkvh, *pWoh;
    cudaGetSymbolAddress((void**)&pQ,    g_Q);
    cudaGetSymbolAddress((void**)&pKV,   g_KV);
    cudaGetSymbolAddress((void**)&pQh,   g_Qh);
    cudaGetSymbolAddress((void**)&pKh,   g_Kh);
    cudaGetSymbolAddress((void**)&pVth,  g_Vth);
    cudaGetSymbolAddress((void**)&pYh,   g_Yh);
    cudaGetSymbolAddress((void**)&pXh,   g_Xh);
    cudaGetSymbolAddress((void**)&pWqh,  g_Wqh);
    cudaGetSymbolAddress((void**)&pWkvh, g_Wkvh);
    cudaGetSymbolAddress((void**)&pWoh,  g_Woh);

    cudaFuncSetAttribute(gemm_f16_nt, cudaFuncAttributeMaxDynamicSharedMemorySize, GEMM_SMEM);
    cudaFuncSetAttribute(attn_f16_kernel, cudaFuncAttributeMaxDynamicSharedMemorySize, ATTN_SMEM);

    // 0) convert GEMM inputs to fp16
    {
        int n;
        n = MROWS * CDIM / 4;  f32_to_f16_kernel<<<(n + 255) / 256, 256>>>(x,   pXh,   n);
        n = CDIM * CDIM / 4;   f32_to_f16_kernel<<<(n + 255) / 256, 256>>>(Wq,  pWqh,  n);
        n = KVW * CDIM / 4;    f32_to_f16_kernel<<<(n + 255) / 256, 256>>>(Wkv, pWkvh, n);
        n = CDIM * CDIM / 4;   f32_to_f16_kernel<<<(n + 255) / 256, 256>>>(Wo,  pWoh,  n);
    }

    // 1) Q = x @ Wq^T ; 2) KV = x @ Wkv^T  (fp16 in, fp32 out)
    gemm_f16_nt<<<dim3(CDIM / 128, MROWS / 128), 256, GEMM_SMEM>>>(pXh, pWqh, pQ, MROWS, CDIM, CDIM);
    gemm_f16_nt<<<dim3(KVW / 128, MROWS / 128), 256, GEMM_SMEM>>>(pXh, pWkvh, pKV, MROWS, KVW, CDIM);

    // 3) RoPE -> fp16 Q/K ; V -> fp16 transposed
    {
        int nq = MROWS * NH * 64;
        rope_q_half<<<(nq + 255) / 256, 256>>>(pQ, pQh);
        int nk = MROWS * NKV * 64;
        rope_k_half<<<(nk + 255) / 256, 256>>>(pKV, pKh);
        v_transpose_half<<<dim3(TSEQ / 32, HD / 32, NB * NKV), dim3(32, 8)>>>(pKV, pVth);
    }

    // 4) fp16 tensor-core causal flash attention (fp16 Y out)
    attn_f16_kernel<<<dim3(TSEQ / 64, NH, NB), 128, ATTN_SMEM>>>(pQh, pKh, pVth, pYh);

    // 5) out = Y @ Wo^T (fp16 in, fp32 out)
    gemm_f16_nt<<<dim3(CDIM / 128, MROWS / 128), 256, GEMM_SMEM>>>(pYh, pWoh, out, MROWS, CDIM, CDIM);
}

// round 12
// speedup vs baseline: 1.1998x; 1.0491x over previous
#include <cuda_runtime.h>
#include <cuda_fp16.h>
#include <math.h>
#include <stdint.h>

// Problem constants
#define NB    2
#define TSEQ  2048
#define CDIM  2048
#define NH    16
#define NKV   4
#define HD    128
#define MROWS (NB * TSEQ)          // 4096
#define KVW   (2 * NKV * HD)       // 1024
#define KVHW  (NKV * HD)           // 512

// Scratch (no cudaMalloc allowed)
__device__ __half g_Qh[(size_t)MROWS * CDIM];
__device__ __half g_Kh[(size_t)MROWS * KVHW];
__device__ __half g_Vth[(size_t)NB * NKV * HD * TSEQ];
__device__ __half g_Yh[(size_t)MROWS * CDIM];
__device__ __half g_Xh[(size_t)MROWS * CDIM];
__device__ __half g_Wqh[(size_t)CDIM * CDIM];
__device__ __half g_Wkvh[(size_t)KVW * CDIM];
__device__ __half g_Woh[(size_t)CDIM * CDIM];

// ---------------------------------------------------------------------------
// Helpers
// ---------------------------------------------------------------------------
__device__ __forceinline__ void mma_f16(float* c,
                                        uint32_t a0, uint32_t a1, uint32_t a2, uint32_t a3,
                                        uint32_t b0, uint32_t b1) {
    asm("mma.sync.aligned.m16n8k16.row.col.f32.f16.f16.f32 "
        "{%0,%1,%2,%3}, {%4,%5,%6,%7}, {%8,%9}, {%0,%1,%2,%3};\n"
        : "+f"(c[0]), "+f"(c[1]), "+f"(c[2]), "+f"(c[3])
        : "r"(a0), "r"(a1), "r"(a2), "r"(a3), "r"(b0), "r"(b1));
}

__device__ __forceinline__ void cp_async16(uint32_t smem_addr, const void* gptr) {
    asm volatile("cp.async.cg.shared.global [%0], [%1], 16;\n"
                 :: "r"(smem_addr), "l"(gptr));
}

// ---------------------------------------------------------------------------
// fp32 -> fp16 conversion (vectorized)
// ---------------------------------------------------------------------------
__global__ void f32_to_f16_kernel(const float* __restrict__ in, __half* __restrict__ out, int n4)
{
    int i = blockIdx.x * blockDim.x + threadIdx.x;
    if (i >= n4) return;
    float4 v = ((const float4*)in)[i];
    ((__half2*)out)[2 * i]     = __floats2half2_rn(v.x, v.y);
    ((__half2*)out)[2 * i + 1] = __floats2half2_rn(v.z, v.w);
}

// ---------------------------------------------------------------------------
// FP16 tensor-core NT GEMM with fused epilogues.
// 128x128 CTA tile, BK=32 halfs, 256 threads (8 warps 2x4), warp tile 64x32,
// 4-stage cp.async ring, ONE __syncthreads per iteration.
// MODE 0: plain fp32 store to C.
// MODE 1: Q projection: rope + 1/sqrt(D) scale -> fp16 O1 (layout [row][H*128]).
// MODE 2: KV projection: bn<512: K rope -> fp16 O1 [row][KV*128];
//                        bn>=512: V transpose -> fp16 O2 [(b,kv,d)][t].
// ---------------------------------------------------------------------------
#define BKH   32
#define PADH  40
#define TILEH (128 * PADH)            // halfs per A (or B) tile (5120)
#define NSTG  4
#define STGH  (2 * TILEH)             // halfs per stage (A+B)
#define GEMM_SMEM (NSTG * STGH * 2)   // 81920 bytes
#define PADE  130                     // fp32 epilogue tile stride (floats)

template <int MODE>
__global__ __launch_bounds__(256, 2) void gemm_f16_nt(
    const __half* __restrict__ A, const __half* __restrict__ B,
    float* __restrict__ C, __half* __restrict__ O1, __half* __restrict__ O2,
    int M, int N, int K)
{
    extern __shared__ __half smh[];

    const int tid  = threadIdx.x;
    const int bm   = blockIdx.y * 128;
    const int bn   = blockIdx.x * 128;
    const int warp = tid >> 5;
    const int lane = tid & 31;
    const int wm   = warp >> 2;        // 0..1
    const int wn   = warp & 3;         // 0..3
    const int gid  = lane >> 2;        // 0..7
    const int tig  = lane & 3;         // 0..3

    const int crow = tid >> 1;
    const int cq   = tid & 1;
    const __half* gA = A + (size_t)(bm + crow) * K + cq * 16;
    const __half* gB = B + (size_t)(bn + crow) * K + cq * 16;
    const int soff = crow * PADH + cq * 16;

    float acc[4][4][4];
#pragma unroll
    for (int mt = 0; mt < 4; mt++)
#pragma unroll
        for (int nt = 0; nt < 4; nt++)
#pragma unroll
            for (int i = 0; i < 4; i++) acc[mt][nt][i] = 0.f;

    const int niter = K / BKH;

    // prologue: stages 0..NSTG-2
#pragma unroll
    for (int p = 0; p < NSTG - 1; p++) {
        const int koff = p * BKH;
        uint32_t sa = (uint32_t)__cvta_generic_to_shared(smh + p * STGH + soff);
        uint32_t sb = sa + TILEH * 2;
#pragma unroll
        for (int j = 0; j < 2; j++) {
            cp_async16(sa + j * 16, gA + koff + j * 8);
            cp_async16(sb + j * 16, gB + koff + j * 8);
        }
        asm volatile("cp.async.commit_group;\n" ::: "memory");
    }

    for (int k0 = 0; k0 < niter; k0++) {
        const int buf = k0 & (NSTG - 1);
        // stage k0 arrived when <= NSTG-2 groups pending
        asm volatile("cp.async.wait_group %0;\n" :: "n"(NSTG - 2) : "memory");
        __syncthreads();   // (a) k0 data visible to all; (b) buffer (k0-1)%NSTG free

        // issue loads for iter k0+NSTG-1 into buffer (k0+NSTG-1)%NSTG == (k0-1)%NSTG
        if (k0 + NSTG - 1 < niter) {
            const int koff = (k0 + NSTG - 1) * BKH;
            uint32_t sa = (uint32_t)__cvta_generic_to_shared(
                smh + ((k0 + NSTG - 1) & (NSTG - 1)) * STGH + soff);
            uint32_t sb = sa + TILEH * 2;
#pragma unroll
            for (int j = 0; j < 2; j++) {
                cp_async16(sa + j * 16, gA + koff + j * 8);
                cp_async16(sb + j * 16, gB + koff + j * 8);
            }
        }
        asm volatile("cp.async.commit_group;\n" ::: "memory");

        const __half* As = smh + buf * STGH;
        const __half* Bs = As + TILEH;
#pragma unroll
        for (int ks = 0; ks < 2; ks++) {
            const int kc = ks * 16;
            uint32_t af[4][4], bf[4][2];
#pragma unroll
            for (int mt = 0; mt < 4; mt++) {
                const int r = wm * 64 + mt * 16 + gid;
                af[mt][0] = *(const uint32_t*)&As[r * PADH + kc + 2 * tig];
                af[mt][1] = *(const uint32_t*)&As[(r + 8) * PADH + kc + 2 * tig];
                af[mt][2] = *(const uint32_t*)&As[r * PADH + kc + 8 + 2 * tig];
                af[mt][3] = *(const uint32_t*)&As[(r + 8) * PADH + kc + 8 + 2 * tig];
            }
#pragma unroll
            for (int nt = 0; nt < 4; nt++) {
                const int r = wn * 32 + nt * 8 + gid;
                bf[nt][0] = *(const uint32_t*)&Bs[r * PADH + kc + 2 * tig];
                bf[nt][1] = *(const uint32_t*)&Bs[r * PADH + kc + 8 + 2 * tig];
            }
#pragma unroll
            for (int mt = 0; mt < 4; mt++)
#pragma unroll
                for (int nt = 0; nt < 4; nt++)
                    mma_f16(acc[mt][nt], af[mt][0], af[mt][1], af[mt][2], af[mt][3],
                            bf[nt][0], bf[nt][1]);
        }
    }

    if (MODE == 0) {
#pragma unroll
        for (int mt = 0; mt < 4; mt++) {
            const int r0 = bm + wm * 64 + mt * 16 + gid;
#pragma unroll
            for (int nt = 0; nt < 4; nt++) {
                const int c0 = bn + wn * 32 + nt * 8 + tig * 2;
                *(float2*)&C[(size_t)r0 * N + c0]       = make_float2(acc[mt][nt][0], acc[mt][nt][1]);
                *(float2*)&C[(size_t)(r0 + 8) * N + c0] = make_float2(acc[mt][nt][2], acc[mt][nt][3]);
            }
        }
        return;
    }

    // ---- fused epilogue via smem fp32 tile [128][PADE] ----
    float* S = (float*)smh;
    __syncthreads();   // all pipeline reads done before smem reuse
#pragma unroll
    for (int mt = 0; mt < 4; mt++) {
        const int r = wm * 64 + mt * 16 + gid;
#pragma unroll
        for (int nt = 0; nt < 4; nt++) {
            const int c = wn * 32 + nt * 8 + tig * 2;
            *(float2*)&S[r * PADE + c]       = make_float2(acc[mt][nt][0], acc[mt][nt][1]);
            *(float2*)&S[(r + 8) * PADE + c] = make_float2(acc[mt][nt][2], acc[mt][nt][3]);
        }
    }
    __syncthreads();

    if (MODE == 1 || (MODE == 2 && bn < KVHW)) {
        // rope rows: pairs (i, i+64) within the single head this tile covers
        const int head = (MODE == 1) ? (bn >> 7) : (bn >> 7);
        const float scale = (MODE == 1) ? 0.08838834764831845f : 1.0f;
        __half* O = (MODE == 1) ? O1 : O1;
        const int rowW = (MODE == 1) ? CDIM : KVHW;
#pragma unroll
        for (int j = 0; j < 32; j++) {
            int p = tid + j * 256;          // 0..8191
            int r = p >> 6, i = p & 63;
            int row = bm + r;
            int t = row & (TSEQ - 1);
            float freq = expf(-(float)i * (9.210340371976184f / 64.0f));
            float sn, cs;
            sincosf((float)t * freq, &sn, &cs);
            float x0 = S[r * PADE + i];
            float x1 = S[r * PADE + i + 64];
            __half* o = O + (size_t)row * rowW + head * 128;
            o[i]      = __float2half((x0 * cs - x1 * sn) * scale);
            o[i + 64] = __float2half((x1 * cs + x0 * sn) * scale);
        }
    } else if (MODE == 2) {
        // V transpose: O2[((b*NKV+kv)*HD + d)*TSEQ + t] = S[r][d]
        const int kv = (bn - KVHW) >> 7;
        const int b  = bm >> 11;           // whole tile in one batch (128 | 2048)
        const int tbase = bm & (TSEQ - 1);
        __half* Obase = O2 + ((size_t)(b * NKV + kv) * HD) * TSEQ + tbase;
#pragma unroll
        for (int j = 0; j < 64; j++) {
            int e = tid + j * 256;          // 0..16383
            int d = e >> 7, r = e & 127;
            Obase[(size_t)d * TSEQ + r] = __float2half(S[r * PADE + d]);
        }
    }
}

// ---------------------------------------------------------------------------
// FP16 tensor-core causal flash attention (fp32 softmax/accum). (R9 body)
// ---------------------------------------------------------------------------
#define KPADH 136
#define VPADH 40
#define PPADH 40
#define KTILEH (32 * KPADH)
#define VTILEH (128 * VPADH)
#define BUFH   (KTILEH + VTILEH)
#define ATTN_SMEM ((2 * BUFH + 64 * PPADH) * 2)   // 43008 bytes

__global__ __launch_bounds__(128, 2) void attn_f16_kernel(
    const __half* __restrict__ Qh, const __half* __restrict__ Kh,
    const __half* __restrict__ Vt, __half* __restrict__ Y)
{
    extern __shared__ __half smh[];
    __half* Ps = smh + 2 * BUFH;

    const int b   = blockIdx.z;
    const int h   = blockIdx.y;
    const int q0  = blockIdx.x * 64;
    const int kvh = h >> 2;
    const int tid  = threadIdx.x;
    const int warp = tid >> 5;
    const int lane = tid & 31;
    const int gid  = lane >> 2;
    const int tig  = lane & 3;

    uint32_t qf[8][4];
    {
        const __half* qp  = Qh + (size_t)(b * TSEQ + q0 + warp * 16 + gid) * CDIM + h * 128;
        const __half* qp8 = qp + 8 * CDIM;
#pragma unroll
        for (int ks = 0; ks < 8; ks++) {
            qf[ks][0] = *(const uint32_t*)&qp [ks * 16 + 2 * tig];
            qf[ks][1] = *(const uint32_t*)&qp8[ks * 16 + 2 * tig];
            qf[ks][2] = *(const uint32_t*)&qp [ks * 16 + 8 + 2 * tig];
            qf[ks][3] = *(const uint32_t*)&qp8[ks * 16 + 8 + 2 * tig];
        }
    }

    float o[16][4];
#pragma unroll
    for (int nt = 0; nt < 16; nt++)
#pragma unroll
        for (int i = 0; i < 4; i++) o[nt][i] = 0.f;
    float m0 = -1e30f, m1 = -1e30f, l0 = 0.f, l1 = 0.f;

    const int nkt = q0 / 32 + 2;

    const __half* Kbase  = Kh + (size_t)(b * TSEQ) * KVHW + kvh * 128;
    const __half* Vtbase = Vt + ((size_t)(b * NKV + kvh) * HD) * TSEQ;

    {
        __half* Kb = smh;
        __half* Vb = smh + KTILEH;
#pragma unroll
        for (int i = 0; i < 4; i++) {
            int idx = tid + i * 128;
            int kr = idx >> 4, kc = idx & 15;
            cp_async16((uint32_t)__cvta_generic_to_shared(Kb + kr * KPADH + kc * 8),
                       Kbase + (size_t)kr * KVHW + kc * 8);
            int vr = idx >> 2, vc = idx & 3;
            cp_async16((uint32_t)__cvta_generic_to_shared(Vb + vr * VPADH + vc * 8),
                       Vtbase + (size_t)vr * TSEQ + vc * 8);
        }
        asm volatile("cp.async.commit_group;\n" ::: "memory");
    }

    const int row0 = warp * 16 + gid;

    for (int t = 0; t < nkt; t++) {
        const int buf = t & 1;
        if (t + 1 < nkt) {
            const int s1 = (t + 1) * 32;
            __half* Kb = smh + (buf ^ 1) * BUFH;
            __half* Vb = Kb + KTILEH;
#pragma unroll
            for (int i = 0; i < 4; i++) {
                int idx = tid + i * 128;
                int kr = idx >> 4, kc = idx & 15;
                cp_async16((uint32_t)__cvta_generic_to_shared(Kb + kr * KPADH + kc * 8),
                           Kbase + (size_t)(s1 + kr) * KVHW + kc * 8);
                int vr = idx >> 2, vc = idx & 3;
                cp_async16((uint32_t)__cvta_generic_to_shared(Vb + vr * VPADH + vc * 8),
                           Vtbase + (size_t)vr * TSEQ + s1 + vc * 8);
            }
        }
        asm volatile("cp.async.commit_group;\n" ::: "memory");
        asm volatile("cp.async.wait_group 1;\n" ::: "memory");
        __syncthreads();

        const __half* Kb = smh + buf * BUFH;
        const __half* Vb = Kb + KTILEH;
        const int s0 = t * 32;

        float s[4][4];
#pragma unroll
        for (int nt = 0; nt < 4; nt++)
#pragma unroll
            for (int i = 0; i < 4; i++) s[nt][i] = 0.f;

#pragma unroll
        for (int ks = 0; ks < 8; ks++) {
            const int kc = ks * 16;
#pragma unroll
            for (int nt = 0; nt < 4; nt++) {
                const __half* kr = Kb + (nt * 8 + gid) * KPADH + kc + 2 * tig;
                uint32_t b0 = *(const uint32_t*)kr;
                uint32_t b1 = *(const uint32_t*)(kr + 8);
                mma_f16(s[nt], qf[ks][0], qf[ks][1], qf[ks][2], qf[ks][3], b0, b1);
            }
        }

        if (t >= nkt - 2) {
            const int r0g = q0 + row0;
#pragma unroll
            for (int nt = 0; nt < 4; nt++) {
                const int c = s0 + nt * 8 + tig * 2;
                if (c > r0g)         s[nt][0] = -1e30f;
                if (c + 1 > r0g)     s[nt][1] = -1e30f;
                if (c > r0g + 8)     s[nt][2] = -1e30f;
                if (c + 1 > r0g + 8) s[nt][3] = -1e30f;
            }
        }

        float rm0 = s[0][0], rm1 = s[0][2];
#pragma unroll
        for (int nt = 0; nt < 4; nt++) {
            rm0 = fmaxf(rm0, fmaxf(s[nt][0], s[nt][1]));
            rm1 = fmaxf(rm1, fmaxf(s[nt][2], s[nt][3]));
        }
        rm0 = fmaxf(rm0, __shfl_xor_sync(0xffffffffu, rm0, 1));
        rm0 = fmaxf(rm0, __shfl_xor_sync(0xffffffffu, rm0, 2));
        rm1 = fmaxf(rm1, __shfl_xor_sync(0xffffffffu, rm1, 1));
        rm1 = fmaxf(rm1, __shfl_xor_sync(0xffffffffu, rm1, 2));

        float mt0 = fmaxf(m0, rm0), mt1 = fmaxf(m1, rm1);
        float c0 = __expf(m0 - mt0), c1 = __expf(m1 - mt1);
        m0 = mt0; m1 = mt1;

        float rs0 = 0.f, rs1 = 0.f;
#pragma unroll
        for (int nt = 0; nt < 4; nt++) {
            s[nt][0] = __expf(s[nt][0] - m0); rs0 += s[nt][0];
            s[nt][1] = __expf(s[nt][1] - m0); rs0 += s[nt][1];
            s[nt][2] = __expf(s[nt][2] - m1); rs1 += s[nt][2];
            s[nt][3] = __expf(s[nt][3] - m1); rs1 += s[nt][3];
        }
        rs0 += __shfl_xor_sync(0xffffffffu, rs0, 1);
        rs0 += __shfl_xor_sync(0xffffffffu, rs0, 2);
        rs1 += __shfl_xor_sync(0xffffffffu, rs1, 1);
        rs1 += __shfl_xor_sync(0xffffffffu, rs1, 2);
        l0 = l0 * c0 + rs0;
        l1 = l1 * c1 + rs1;

#pragma unroll
        for (int nt = 0; nt < 16; nt++) {
            o[nt][0] *= c0; o[nt][1] *= c0;
            o[nt][2] *= c1; o[nt][3] *= c1;
        }

#pragma unroll
        for (int nt = 0; nt < 4; nt++) {
            *(__half2*)&Ps[row0 * PPADH + nt * 8 + 2 * tig]       = __floats2half2_rn(s[nt][0], s[nt][1]);
            *(__half2*)&Ps[(row0 + 8) * PPADH + nt * 8 + 2 * tig] = __floats2half2_rn(s[nt][2], s[nt][3]);
        }
        __syncwarp();

#pragma unroll
        for (int ks = 0; ks < 2; ks++) {
            const int kc = ks * 16;
            uint32_t a0 = *(const uint32_t*)&Ps[row0 * PPADH + kc + 2 * tig];
            uint32_t a1 = *(const uint32_t*)&Ps[(row0 + 8) * PPADH + kc + 2 * tig];
            uint32_t a2 = *(const uint32_t*)&Ps[row0 * PPADH + kc + 8 + 2 * tig];
            uint32_t a3 = *(const uint32_t*)&Ps[(row0 + 8) * PPADH + kc + 8 + 2 * tig];
#pragma unroll
            for (int nt = 0; nt < 16; nt++) {
                const __half* vr = Vb + (nt * 8 + gid) * VPADH + kc + 2 * tig;
                uint32_t b0 = *(const uint32_t*)vr;
                uint32_t b1 = *(const uint32_t*)(vr + 8);
                mma_f16(o[nt], a0, a1, a2, a3, b0, b1);
            }
        }
        __syncthreads();
    }

    const float inv0 = 1.f / l0, inv1 = 1.f / l1;
    __half* yp  = Y + (size_t)(b * TSEQ + q0 + row0) * CDIM + h * 128;
    __half* yp8 = yp + 8 * CDIM;
#pragma unroll
    for (int nt = 0; nt < 16; nt++) {
        const int c = nt * 8 + tig * 2;
        *(__half2*)&yp [c] = __floats2half2_rn(o[nt][0] * inv0, o[nt][1] * inv0);
        *(__half2*)&yp8[c] = __floats2half2_rn(o[nt][2] * inv1, o[nt][3] * inv1);
    }
}

// ---------------------------------------------------------------------------
extern "C" void kernel_launch(void* const* d_in, const int* in_sizes, int n_in,
                              void* d_out, int out_size)
{
    const float* x   = (const float*)d_in[0];
    const float* Wq  = (const float*)d_in[1];
    const float* Wkv = (const float*)d_in[2];
    const float* Wo  = (const float*)d_in[3];
    float* out = (float*)d_out;

    __half *pQh, *pKh, *pVth, *pYh, *pXh, *pWqh, *pWkvh, *pWoh;
    cudaGetSymbolAddress((void**)&pQh,   g_Qh);
    cudaGetSymbolAddress((void**)&pKh,   g_Kh);
    cudaGetSymbolAddress((void**)&pVth,  g_Vth);
    cudaGetSymbolAddress((void**)&pYh,   g_Yh);
    cudaGetSymbolAddress((void**)&pXh,   g_Xh);
    cudaGetSymbolAddress((void**)&pWqh,  g_Wqh);
    cudaGetSymbolAddress((void**)&pWkvh, g_Wkvh);
    cudaGetSymbolAddress((void**)&pWoh,  g_Woh);

    cudaFuncSetAttribute(gemm_f16_nt<0>, cudaFuncAttributeMaxDynamicSharedMemorySize, GEMM_SMEM);
    cudaFuncSetAttribute(gemm_f16_nt<1>, cudaFuncAttributeMaxDynamicSharedMemorySize, GEMM_SMEM);
    cudaFuncSetAttribute(gemm_f16_nt<2>, cudaFuncAttributeMaxDynamicSharedMemorySize, GEMM_SMEM);
    cudaFuncSetAttribute(attn_f16_kernel, cudaFuncAttributeMaxDynamicSharedMemorySize, ATTN_SMEM);

    // 0) convert GEMM inputs to fp16
    {
        int n;
        n = MROWS * CDIM / 4;  f32_to_f16_kernel<<<(n + 255) / 256, 256>>>(x,   pXh,   n);
        n = CDIM * CDIM / 4;   f32_to_f16_kernel<<<(n + 255) / 256, 256>>>(Wq,  pWqh,  n);
        n = KVW * CDIM / 4;    f32_to_f16_kernel<<<(n + 255) / 256, 256>>>(Wkv, pWkvh, n);
        n = CDIM * CDIM / 4;   f32_to_f16_kernel<<<(n + 255) / 256, 256>>>(Wo,  pWoh,  n);
    }

    // 1) Q projection with fused rope+scale -> g_Qh
    gemm_f16_nt<1><<<dim3(CDIM / 128, MROWS / 128), 256, GEMM_SMEM>>>(
        pXh, pWqh, nullptr, pQh, nullptr, MROWS, CDIM, CDIM);
    // 2) KV projection with fused K-rope -> g_Kh and V-transpose -> g_Vth
    gemm_f16_nt<2><<<dim3(KVW / 128, MROWS / 128), 256, GEMM_SMEM>>>(
        pXh, pWkvh, nullptr, pKh, pVth, MROWS, KVW, CDIM);

    // 3) fp16 tensor-core causal flash attention (fp16 Y out)
    attn_f16_kernel<<<dim3(TSEQ / 64, NH, NB), 128, ATTN_SMEM>>>(pQh, pKh, pVth, pYh);

    // 4) out = Y @ Wo^T (fp16 in, fp32 out)
    gemm_f16_nt<0><<<dim3(CDIM / 128, MROWS / 128), 256, GEMM_SMEM>>>(
        pYh, pWoh, out, nullptr, nullptr, MROWS, CDIM, CDIM);
}

// round 13
// speedup vs baseline: 1.2293x; 1.0246x over previous
#include <cuda_runtime.h>
#include <cuda_fp16.h>
#include <math.h>
#include <stdint.h>

// Problem constants
#define NB    2
#define TSEQ  2048
#define CDIM  2048
#define NH    16
#define NKV   4
#define HD    128
#define MROWS (NB * TSEQ)          // 4096
#define KVW   (2 * NKV * HD)       // 1024
#define KVHW  (NKV * HD)           // 512

// Scratch (no cudaMalloc allowed)
__device__ __half g_Qh[(size_t)MROWS * CDIM];
__device__ __half g_Kh[(size_t)MROWS * KVHW];
__device__ __half g_Vth[(size_t)NB * NKV * HD * TSEQ];
__device__ __half g_Yh[(size_t)MROWS * CDIM];
__device__ __half g_Xh[(size_t)MROWS * CDIM];
__device__ __half g_Wqh[(size_t)CDIM * CDIM];
__device__ __half g_Wkvh[(size_t)KVW * CDIM];
__device__ __half g_Woh[(size_t)CDIM * CDIM];

// ---------------------------------------------------------------------------
// Helpers
// ---------------------------------------------------------------------------
__device__ __forceinline__ void mma_f16(float* c,
                                        uint32_t a0, uint32_t a1, uint32_t a2, uint32_t a3,
                                        uint32_t b0, uint32_t b1) {
    asm("mma.sync.aligned.m16n8k16.row.col.f32.f16.f16.f32 "
        "{%0,%1,%2,%3}, {%4,%5,%6,%7}, {%8,%9}, {%0,%1,%2,%3};\n"
        : "+f"(c[0]), "+f"(c[1]), "+f"(c[2]), "+f"(c[3])
        : "r"(a0), "r"(a1), "r"(a2), "r"(a3), "r"(b0), "r"(b1));
}

__device__ __forceinline__ void cp_async16(uint32_t smem_addr, const void* gptr) {
    asm volatile("cp.async.cg.shared.global [%0], [%1], 16;\n"
                 :: "r"(smem_addr), "l"(gptr));
}

// ---------------------------------------------------------------------------
// fp32 -> fp16 conversion for all four inputs in ONE launch
// ---------------------------------------------------------------------------
#define N4_X   (MROWS * CDIM / 4)
#define N4_WQ  (CDIM * CDIM / 4)
#define N4_WKV (KVW * CDIM / 4)
#define N4_WO  (CDIM * CDIM / 4)
#define N4_ALL (N4_X + N4_WQ + N4_WKV + N4_WO)

__global__ void cvt_all_kernel(const float* __restrict__ x, const float* __restrict__ wq,
                               const float* __restrict__ wkv, const float* __restrict__ wo,
                               __half* __restrict__ xh, __half* __restrict__ wqh,
                               __half* __restrict__ wkvh, __half* __restrict__ woh)
{
    int i = blockIdx.x * blockDim.x + threadIdx.x;
    const float* in;
    __half* out;
    int j = i;
    if (i < N4_X)                     { in = x;   out = xh;   }
    else if ((j -= N4_X)   < N4_WQ)   { in = wq;  out = wqh;  }
    else if ((j -= N4_WQ)  < N4_WKV)  { in = wkv; out = wkvh; }
    else if ((j -= N4_WKV) < N4_WO)   { in = wo;  out = woh;  }
    else return;
    float4 v = ((const float4*)in)[j];
    ((__half2*)out)[2 * j]     = __floats2half2_rn(v.x, v.y);
    ((__half2*)out)[2 * j + 1] = __floats2half2_rn(v.z, v.w);
}

// ---------------------------------------------------------------------------
// FP16 tensor-core NT GEMM with fused epilogues.
// 128x128 CTA tile, BK=32 halfs, 256 threads (8 warps 2x4), warp tile 64x32,
// 4-stage cp.async ring, ONE __syncthreads per iteration.
// MODE 0: plain fp32 store to C (B = Bq).
// MODE 3: fused QKV: blockIdx.x < 16 -> Q proj (B=Bq, rope+scale -> O1=Qh);
//         else KV proj (B=Bkv): bn<512: K rope -> O2=Kh; else V^T -> O3=Vth.
// ---------------------------------------------------------------------------
#define BKH   32
#define PADH  40
#define TILEH (128 * PADH)            // halfs per A (or B) tile (5120)
#define NSTG  4
#define STGH  (2 * TILEH)             // halfs per stage (A+B)
#define GEMM_SMEM (NSTG * STGH * 2)   // 81920 bytes
#define PADE  130                     // fp32 epilogue tile stride (floats)

template <int MODE>
__global__ __launch_bounds__(256, 2) void gemm_f16_nt(
    const __half* __restrict__ A, const __half* __restrict__ Bq,
    const __half* __restrict__ Bkv,
    float* __restrict__ C, __half* __restrict__ O1, __half* __restrict__ O2,
    __half* __restrict__ O3, int M, int N, int K)
{
    extern __shared__ __half smh[];

    const int tid  = threadIdx.x;
    const int bm   = blockIdx.y * 128;
    const int warp = tid >> 5;
    const int lane = tid & 31;
    const int wm   = warp >> 2;        // 0..1
    const int wn   = warp & 3;         // 0..3
    const int gid  = lane >> 2;        // 0..7
    const int tig  = lane & 3;         // 0..3

    // B selection (MODE 3: Q tiles then KV tiles)
    const bool isQ = (MODE != 3) || (blockIdx.x < CDIM / 128);
    const __half* Bsel = (MODE == 3 && !isQ) ? Bkv : Bq;
    const int bn = (MODE == 3 && !isQ) ? (blockIdx.x - CDIM / 128) * 128
                                       : blockIdx.x * 128;

    const int crow = tid >> 1;
    const int cq   = tid & 1;
    const __half* gA = A + (size_t)(bm + crow) * K + cq * 16;
    const __half* gB = Bsel + (size_t)(bn + crow) * K + cq * 16;
    const int soff = crow * PADH + cq * 16;

    float acc[4][4][4];
#pragma unroll
    for (int mt = 0; mt < 4; mt++)
#pragma unroll
        for (int nt = 0; nt < 4; nt++)
#pragma unroll
            for (int i = 0; i < 4; i++) acc[mt][nt][i] = 0.f;

    const int niter = K / BKH;

    // prologue: stages 0..NSTG-2
#pragma unroll
    for (int p = 0; p < NSTG - 1; p++) {
        const int koff = p * BKH;
        uint32_t sa = (uint32_t)__cvta_generic_to_shared(smh + p * STGH + soff);
        uint32_t sb = sa + TILEH * 2;
#pragma unroll
        for (int j = 0; j < 2; j++) {
            cp_async16(sa + j * 16, gA + koff + j * 8);
            cp_async16(sb + j * 16, gB + koff + j * 8);
        }
        asm volatile("cp.async.commit_group;\n" ::: "memory");
    }

    for (int k0 = 0; k0 < niter; k0++) {
        const int buf = k0 & (NSTG - 1);
        asm volatile("cp.async.wait_group %0;\n" :: "n"(NSTG - 2) : "memory");
        __syncthreads();   // (a) stage k0 visible; (b) buffer (k0-1)%NSTG free

        if (k0 + NSTG - 1 < niter) {
            const int koff = (k0 + NSTG - 1) * BKH;
            uint32_t sa = (uint32_t)__cvta_generic_to_shared(
                smh + ((k0 + NSTG - 1) & (NSTG - 1)) * STGH + soff);
            uint32_t sb = sa + TILEH * 2;
#pragma unroll
            for (int j = 0; j < 2; j++) {
                cp_async16(sa + j * 16, gA + koff + j * 8);
                cp_async16(sb + j * 16, gB + koff + j * 8);
            }
        }
        asm volatile("cp.async.commit_group;\n" ::: "memory");

        const __half* As = smh + buf * STGH;
        const __half* Bs = As + TILEH;
#pragma unroll
        for (int ks = 0; ks < 2; ks++) {
            const int kc = ks * 16;
            uint32_t af[4][4], bf[4][2];
#pragma unroll
            for (int mt = 0; mt < 4; mt++) {
                const int r = wm * 64 + mt * 16 + gid;
                af[mt][0] = *(const uint32_t*)&As[r * PADH + kc + 2 * tig];
                af[mt][1] = *(const uint32_t*)&As[(r + 8) * PADH + kc + 2 * tig];
                af[mt][2] = *(const uint32_t*)&As[r * PADH + kc + 8 + 2 * tig];
                af[mt][3] = *(const uint32_t*)&As[(r + 8) * PADH + kc + 8 + 2 * tig];
            }
#pragma unroll
            for (int nt = 0; nt < 4; nt++) {
                const int r = wn * 32 + nt * 8 + gid;
                bf[nt][0] = *(const uint32_t*)&Bs[r * PADH + kc + 2 * tig];
                bf[nt][1] = *(const uint32_t*)&Bs[r * PADH + kc + 8 + 2 * tig];
            }
#pragma unroll
            for (int mt = 0; mt < 4; mt++)
#pragma unroll
                for (int nt = 0; nt < 4; nt++)
                    mma_f16(acc[mt][nt], af[mt][0], af[mt][1], af[mt][2], af[mt][3],
                            bf[nt][0], bf[nt][1]);
        }
    }

    if (MODE == 0) {
#pragma unroll
        for (int mt = 0; mt < 4; mt++) {
            const int r0 = bm + wm * 64 + mt * 16 + gid;
#pragma unroll
            for (int nt = 0; nt < 4; nt++) {
                const int c0 = bn + wn * 32 + nt * 8 + tig * 2;
                *(float2*)&C[(size_t)r0 * N + c0]       = make_float2(acc[mt][nt][0], acc[mt][nt][1]);
                *(float2*)&C[(size_t)(r0 + 8) * N + c0] = make_float2(acc[mt][nt][2], acc[mt][nt][3]);
            }
        }
        return;
    }

    // ---- fused epilogue via smem fp32 tile [128][PADE] ----
    float* S = (float*)smh;
    __syncthreads();   // all pipeline reads done before smem reuse
#pragma unroll
    for (int mt = 0; mt < 4; mt++) {
        const int r = wm * 64 + mt * 16 + gid;
#pragma unroll
        for (int nt = 0; nt < 4; nt++) {
            const int c = wn * 32 + nt * 8 + tig * 2;
            *(float2*)&S[r * PADE + c]       = make_float2(acc[mt][nt][0], acc[mt][nt][1]);
            *(float2*)&S[(r + 8) * PADE + c] = make_float2(acc[mt][nt][2], acc[mt][nt][3]);
        }
    }
    __syncthreads();

    if (isQ || bn < KVHW) {
        // rope rows: pairs (i, i+64) within the single head this tile covers
        const int head = bn >> 7;
        const float scale = isQ ? 0.08838834764831845f : 1.0f;
        __half* O = isQ ? O1 : O2;
        const int rowW = isQ ? CDIM : KVHW;
#pragma unroll
        for (int j = 0; j < 32; j++) {
            int p = tid + j * 256;          // 0..8191
            int r = p >> 6, i = p & 63;
            int row = bm + r;
            int t = row & (TSEQ - 1);
            float freq = expf(-(float)i * (9.210340371976184f / 64.0f));
            float sn, cs;
            sincosf((float)t * freq, &sn, &cs);
            float x0 = S[r * PADE + i];
            float x1 = S[r * PADE + i + 64];
            __half* o = O + (size_t)row * rowW + head * 128;
            o[i]      = __float2half((x0 * cs - x1 * sn) * scale);
            o[i + 64] = __float2half((x1 * cs + x0 * sn) * scale);
        }
    } else {
        // V transpose: O3[((b*NKV+kv)*HD + d)*TSEQ + t] = S[r][d]
        const int kv = (bn - KVHW) >> 7;
        const int b  = bm >> 11;
        const int tbase = bm & (TSEQ - 1);
        __half* Obase = O3 + ((size_t)(b * NKV + kv) * HD) * TSEQ + tbase;
#pragma unroll
        for (int j = 0; j < 64; j++) {
            int e = tid + j * 256;          // 0..16383
            int d = e >> 7, r = e & 127;
            Obase[(size_t)d * TSEQ + r] = __float2half(S[r * PADE + d]);
        }
    }
}

// ---------------------------------------------------------------------------
// FP16 tensor-core causal flash attention (fp32 softmax/accum).
// Heaviest-first scheduling: q0 decreases with blockIdx.x so long CTAs
// launch in the first waves.
// ---------------------------------------------------------------------------
#define KPADH 136
#define VPADH 40
#define PPADH 40
#define KTILEH (32 * KPADH)
#define VTILEH (128 * VPADH)
#define BUFH   (KTILEH + VTILEH)
#define ATTN_SMEM ((2 * BUFH + 64 * PPADH) * 2)   // 43008 bytes

__global__ __launch_bounds__(128, 2) void attn_f16_kernel(
    const __half* __restrict__ Qh, const __half* __restrict__ Kh,
    const __half* __restrict__ Vt, __half* __restrict__ Y)
{
    extern __shared__ __half smh[];
    __half* Ps = smh + 2 * BUFH;

    const int b   = blockIdx.z;
    const int h   = blockIdx.y;
    const int q0  = (int)(gridDim.x - 1 - blockIdx.x) * 64;   // heaviest first
    const int kvh = h >> 2;
    const int tid  = threadIdx.x;
    const int warp = tid >> 5;
    const int lane = tid & 31;
    const int gid  = lane >> 2;
    const int tig  = lane & 3;

    uint32_t qf[8][4];
    {
        const __half* qp  = Qh + (size_t)(b * TSEQ + q0 + warp * 16 + gid) * CDIM + h * 128;
        const __half* qp8 = qp + 8 * CDIM;
#pragma unroll
        for (int ks = 0; ks < 8; ks++) {
            qf[ks][0] = *(const uint32_t*)&qp [ks * 16 + 2 * tig];
            qf[ks][1] = *(const uint32_t*)&qp8[ks * 16 + 2 * tig];
            qf[ks][2] = *(const uint32_t*)&qp [ks * 16 + 8 + 2 * tig];
            qf[ks][3] = *(const uint32_t*)&qp8[ks * 16 + 8 + 2 * tig];
        }
    }

    float o[16][4];
#pragma unroll
    for (int nt = 0; nt < 16; nt++)
#pragma unroll
        for (int i = 0; i < 4; i++) o[nt][i] = 0.f;
    float m0 = -1e30f, m1 = -1e30f, l0 = 0.f, l1 = 0.f;

    const int nkt = q0 / 32 + 2;

    const __half* Kbase  = Kh + (size_t)(b * TSEQ) * KVHW + kvh * 128;
    const __half* Vtbase = Vt + ((size_t)(b * NKV + kvh) * HD) * TSEQ;

    {
        __half* Kb = smh;
        __half* Vb = smh + KTILEH;
#pragma unroll
        for (int i = 0; i < 4; i++) {
            int idx = tid + i * 128;
            int kr = idx >> 4, kc = idx & 15;
            cp_async16((uint32_t)__cvta_generic_to_shared(Kb + kr * KPADH + kc * 8),
                       Kbase + (size_t)kr * KVHW + kc * 8);
            int vr = idx >> 2, vc = idx & 3;
            cp_async16((uint32_t)__cvta_generic_to_shared(Vb + vr * VPADH + vc * 8),
                       Vtbase + (size_t)vr * TSEQ + vc * 8);
        }
        asm volatile("cp.async.commit_group;\n" ::: "memory");
    }

    const int row0 = warp * 16 + gid;

    for (int t = 0; t < nkt; t++) {
        const int buf = t & 1;
        if (t + 1 < nkt) {
            const int s1 = (t + 1) * 32;
            __half* Kb = smh + (buf ^ 1) * BUFH;
            __half* Vb = Kb + KTILEH;
#pragma unroll
            for (int i = 0; i < 4; i++) {
                int idx = tid + i * 128;
                int kr = idx >> 4, kc = idx & 15;
                cp_async16((uint32_t)__cvta_generic_to_shared(Kb + kr * KPADH + kc * 8),
                           Kbase + (size_t)(s1 + kr) * KVHW + kc * 8);
                int vr = idx >> 2, vc = idx & 3;
                cp_async16((uint32_t)__cvta_generic_to_shared(Vb + vr * VPADH + vc * 8),
                           Vtbase + (size_t)vr * TSEQ + s1 + vc * 8);
            }
        }
        asm volatile("cp.async.commit_group;\n" ::: "memory");
        asm volatile("cp.async.wait_group 1;\n" ::: "memory");
        __syncthreads();

        const __half* Kb = smh + buf * BUFH;
        const __half* Vb = Kb + KTILEH;
        const int s0 = t * 32;

        float s[4][4];
#pragma unroll
        for (int nt = 0; nt < 4; nt++)
#pragma unroll
            for (int i = 0; i < 4; i++) s[nt][i] = 0.f;

#pragma unroll
        for (int ks = 0; ks < 8; ks++) {
            const int kc = ks * 16;
#pragma unroll
            for (int nt = 0; nt < 4; nt++) {
                const __half* kr = Kb + (nt * 8 + gid) * KPADH + kc + 2 * tig;
                uint32_t b0 = *(const uint32_t*)kr;
                uint32_t b1 = *(const uint32_t*)(kr + 8);
                mma_f16(s[nt], qf[ks][0], qf[ks][1], qf[ks][2], qf[ks][3], b0, b1);
            }
        }

        if (t >= nkt - 2) {
            const int r0g = q0 + row0;
#pragma unroll
            for (int nt = 0; nt < 4; nt++) {
                const int c = s0 + nt * 8 + tig * 2;
                if (c > r0g)         s[nt][0] = -1e30f;
                if (c + 1 > r0g)     s[nt][1] = -1e30f;
                if (c > r0g + 8)     s[nt][2] = -1e30f;
                if (c + 1 > r0g + 8) s[nt][3] = -1e30f;
            }
        }

        float rm0 = s[0][0], rm1 = s[0][2];
#pragma unroll
        for (int nt = 0; nt < 4; nt++) {
            rm0 = fmaxf(rm0, fmaxf(s[nt][0], s[nt][1]));
            rm1 = fmaxf(rm1, fmaxf(s[nt][2], s[nt][3]));
        }
        rm0 = fmaxf(rm0, __shfl_xor_sync(0xffffffffu, rm0, 1));
        rm0 = fmaxf(rm0, __shfl_xor_sync(0xffffffffu, rm0, 2));
        rm1 = fmaxf(rm1, __shfl_xor_sync(0xffffffffu, rm1, 1));
        rm1 = fmaxf(rm1, __shfl_xor_sync(0xffffffffu, rm1, 2));

        float mt0 = fmaxf(m0, rm0), mt1 = fmaxf(m1, rm1);
        float c0 = __expf(m0 - mt0), c1 = __expf(m1 - mt1);
        m0 = mt0; m1 = mt1;

        float rs0 = 0.f, rs1 = 0.f;
#pragma unroll
        for (int nt = 0; nt < 4; nt++) {
            s[nt][0] = __expf(s[nt][0] - m0); rs0 += s[nt][0];
            s[nt][1] = __expf(s[nt][1] - m0); rs0 += s[nt][1];
            s[nt][2] = __expf(s[nt][2] - m1); rs1 += s[nt][2];
            s[nt][3] = __expf(s[nt][3] - m1); rs1 += s[nt][3];
        }
        rs0 += __shfl_xor_sync(0xffffffffu, rs0, 1);
        rs0 += __shfl_xor_sync(0xffffffffu, rs0, 2);
        rs1 += __shfl_xor_sync(0xffffffffu, rs1, 1);
        rs1 += __shfl_xor_sync(0xffffffffu, rs1, 2);
        l0 = l0 * c0 + rs0;
        l1 = l1 * c1 + rs1;

#pragma unroll
        for (int nt = 0; nt < 16; nt++) {
            o[nt][0] *= c0; o[nt][1] *= c0;
            o[nt][2] *= c1; o[nt][3] *= c1;
        }

#pragma unroll
        for (int nt = 0; nt < 4; nt++) {
            *(__half2*)&Ps[row0 * PPADH + nt * 8 + 2 * tig]       = __floats2half2_rn(s[nt][0], s[nt][1]);
            *(__half2*)&Ps[(row0 + 8) * PPADH + nt * 8 + 2 * tig] = __floats2half2_rn(s[nt][2], s[nt][3]);
        }
        __syncwarp();

#pragma unroll
        for (int ks = 0; ks < 2; ks++) {
            const int kc = ks * 16;
            uint32_t a0 = *(const uint32_t*)&Ps[row0 * PPADH + kc + 2 * tig];
            uint32_t a1 = *(const uint32_t*)&Ps[(row0 + 8) * PPADH + kc + 2 * tig];
            uint32_t a2 = *(const uint32_t*)&Ps[row0 * PPADH + kc + 8 + 2 * tig];
            uint32_t a3 = *(const uint32_t*)&Ps[(row0 + 8) * PPADH + kc + 8 + 2 * tig];
#pragma unroll
            for (int nt = 0; nt < 16; nt++) {
                const __half* vr = Vb + (nt * 8 + gid) * VPADH + kc + 2 * tig;
                uint32_t b0 = *(const uint32_t*)vr;
                uint32_t b1 = *(const uint32_t*)(vr + 8);
                mma_f16(o[nt], a0, a1, a2, a3, b0, b1);
            }
        }
        __syncthreads();
    }

    const float inv0 = 1.f / l0, inv1 = 1.f / l1;
    __half* yp  = Y + (size_t)(b * TSEQ + q0 + row0) * CDIM + h * 128;
    __half* yp8 = yp + 8 * CDIM;
#pragma unroll
    for (int nt = 0; nt < 16; nt++) {
        const int c = nt * 8 + tig * 2;
        *(__half2*)&yp [c] = __floats2half2_rn(o[nt][0] * inv0, o[nt][1] * inv0);
        *(__half2*)&yp8[c] = __floats2half2_rn(o[nt][2] * inv1, o[nt][3] * inv1);
    }
}

// ---------------------------------------------------------------------------
extern "C" void kernel_launch(void* const* d_in, const int* in_sizes, int n_in,
                              void* d_out, int out_size)
{
    const float* x   = (const float*)d_in[0];
    const float* Wq  = (const float*)d_in[1];
    const float* Wkv = (const float*)d_in[2];
    const float* Wo  = (const float*)d_in[3];
    float* out = (float*)d_out;

    __half *pQh, *pKh, *pVth, *pYh, *pXh, *pWqh, *pWkvh, *pWoh;
    cudaGetSymbolAddress((void**)&pQh,   g_Qh);
    cudaGetSymbolAddress((void**)&pKh,   g_Kh);
    cudaGetSymbolAddress((void**)&pVth,  g_Vth);
    cudaGetSymbolAddress((void**)&pYh,   g_Yh);
    cudaGetSymbolAddress((void**)&pXh,   g_Xh);
    cudaGetSymbolAddress((void**)&pWqh,  g_Wqh);
    cudaGetSymbolAddress((void**)&pWkvh, g_Wkvh);
    cudaGetSymbolAddress((void**)&pWoh,  g_Woh);

    cudaFuncSetAttribute(gemm_f16_nt<0>, cudaFuncAttributeMaxDynamicSharedMemorySize, GEMM_SMEM);
    cudaFuncSetAttribute(gemm_f16_nt<3>, cudaFuncAttributeMaxDynamicSharedMemorySize, GEMM_SMEM);
    cudaFuncSetAttribute(attn_f16_kernel, cudaFuncAttributeMaxDynamicSharedMemorySize, ATTN_SMEM);

    // 0) convert all four inputs to fp16 in one launch
    cvt_all_kernel<<<(N4_ALL + 255) / 256, 256>>>(x, Wq, Wkv, Wo, pXh, pWqh, pWkvh, pWoh);

    // 1) fused QKV projection (Q: rope+scale -> Qh; K: rope -> Kh; V: ^T -> Vth)
    gemm_f16_nt<3><<<dim3((CDIM + KVW) / 128, MROWS / 128), 256, GEMM_SMEM>>>(
        pXh, pWqh, pWkvh, nullptr, pQh, pKh, pVth, MROWS, 0, CDIM);

    // 2) fp16 tensor-core causal flash attention (fp16 Y out)
    attn_f16_kernel<<<dim3(TSEQ / 64, NH, NB), 128, ATTN_SMEM>>>(pQh, pKh, pVth, pYh);

    // 3) out = Y @ Wo^T (fp16 in, fp32 out)
    gemm_f16_nt<0><<<dim3(CDIM / 128, MROWS / 128), 256, GEMM_SMEM>>>(
        pYh, pWoh, nullptr, out, nullptr, nullptr, nullptr, MROWS, CDIM, CDIM);
}